// round 9
// baseline (speedup 1.0000x reference)
#include <cuda_runtime.h>
#include <cstdint>

#define NN 200000
#define EE 8192
#define HH 64
#define EAA 32
#define AA 50
#define DF 128

#define NBLK 148
#define NTHR 1024
#define NWARP (NTHR / 32)
#define TOTWARP (NBLK * NWARP)

typedef unsigned long long u64;

// ---- persist shared memory layout (floats) ----
#define WMT_STRIDE 196
#define OFF_WMT 0
#define SZ_WMT (64 * WMT_STRIDE)            // 12544 (W_msg transposed, padded stride)
#define OFF_WIH (OFF_WMT + SZ_WMT)          // 12544
#define OFF_WHH (OFF_WIH + 16384)           // 28928
#define OFF_BM  (OFF_WHH + 16384)           // 45312
#define OFF_BL  (OFF_BM + 64)               // 45376
#define OFF_TW  (OFF_BL + 256)              // 45632
#define OFF_TB  (OFF_TW + 32)               // 45664
#define OFF_FEAT (OFF_TB + 32)              // 45696  (NWARP * 192)
#define OFF_M   (OFF_FEAT + NWARP * 192)    // 51840  (NWARP * 128)
#define SMEM_FLOATS (OFF_M + NWARP * 128)   // 55936
#define SMEM_BYTES (SMEM_FLOATS * 4)        // 223744 (< 232448 cap)

// ---- device scratch ----
__device__ float g_h[(size_t)NN * HH];
__device__ float g_c[(size_t)NN * HH];
__device__ int   g_done[EE];
__device__ int   g_prev_s[EE];
__device__ int   g_prev_d[EE];
__device__ int   g_head[NN];
__device__ int   g_next[2 * EE];
__device__ float g_Wc[192 * AA];
__device__ float g_bc[AA];
__device__ unsigned g_bar_cnt;
__device__ volatile unsigned g_bar_gen;

// ---- f32x2 packed math (Blackwell FFMA2; ptxas never auto-fuses this) ----
__device__ __forceinline__ u64 fma2(u64 a, u64 b, u64 c) {
    u64 d;
    asm("fma.rn.f32x2 %0, %1, %2, %3;" : "=l"(d) : "l"(a), "l"(b), "l"(c));
    return d;
}
__device__ __forceinline__ u64 pack2(float lo, float hi) {
    u64 r;
    asm("mov.b64 %0, {%1, %2};" : "=l"(r) : "f"(lo), "f"(hi));
    return r;
}
__device__ __forceinline__ float2 unpack2(u64 v) {
    float2 f;
    asm("mov.b64 {%0, %1}, %2;" : "=f"(f.x), "=f"(f.y) : "l"(v));
    return f;
}

__device__ __forceinline__ void grid_bar() {
    __syncthreads();
    if (threadIdx.x == 0) {
        __threadfence();
        unsigned gen = g_bar_gen;
        if (atomicAdd(&g_bar_cnt, 1u) == (unsigned)(gridDim.x - 1u)) {
            g_bar_cnt = 0u;
            __threadfence();
            g_bar_gen = gen + 1u;
        } else {
            while (g_bar_gen == gen) __nanosleep(128);
            __threadfence();
        }
    }
    __syncthreads();
}

__device__ __forceinline__ float sigf(float v) { return 1.0f / (1.0f + __expf(-v)); }
__device__ __forceinline__ float tanhf_(float v) {
    float e = __expf(2.0f * v);
    return 1.0f - 2.0f / (e + 1.0f);
}

// ---- init: node-chain heads, zero touched h/c, fuse W_emb@W_cls, reset flags ----
__global__ void __launch_bounds__(512) k_init(const int* __restrict__ ei,
                                              const float* __restrict__ Wemb,
                                              const float* __restrict__ bemb,
                                              const float* __restrict__ Wcls,
                                              const float* __restrict__ bcls) {
    int t = blockIdx.x * blockDim.x + threadIdx.x;  // 65536 threads
    if (t < 2 * EE) g_head[ei[t]] = -1;
    {   // 4 threads per endpoint zero h/c (dupes benign)
        int ep = t >> 2, part = t & 3;
        if (ep < 2 * EE) {
            int v = ei[ep];
            float4 z = make_float4(0.f, 0.f, 0.f, 0.f);
            float4* hp = (float4*)(g_h + (size_t)v * HH + part * 16);
            float4* cp = (float4*)(g_c + (size_t)v * HH + part * 16);
#pragma unroll
            for (int i = 0; i < 4; i++) { hp[i] = z; cp[i] = z; }
        }
    }
    if (t < EE) g_done[t] = 0;
    if (t < 192 * AA) {
        int k = t / AA, a = t - k * AA;
        float s = 0.0f;
        const float* wr = Wemb + k * HH;
#pragma unroll 8
        for (int j = 0; j < HH; j++) s = fmaf(wr[j], Wcls[j * AA + a], s);
        g_Wc[t] = s;
    }
    if (t < AA) {
        float s = bcls[t];
        for (int j = 0; j < HH; j++) s = fmaf(bemb[j], Wcls[j * AA + t], s);
        g_bc[t] = s;
    }
    if (t == 0) { g_bar_cnt = 0u; g_bar_gen = 0u; }
}

// ---- build per-node endpoint chains (unordered) ----
__global__ void __launch_bounds__(512) k_chain(const int* __restrict__ ei) {
    int t = blockIdx.x * blockDim.x + threadIdx.x;
    if (t < 2 * EE) g_next[t] = atomicExch(&g_head[ei[t]], t);
}

// ---- extract immediate predecessor per endpoint (chains are ~1 entry avg) ----
__global__ void __launch_bounds__(512) k_prevk(const int* __restrict__ ei) {
    int t = blockIdx.x * blockDim.x + threadIdx.x;
    if (t >= 2 * EE) return;
    int v = ei[t];
    int e = (t < EE) ? t : t - EE;
    int best = -1;
    for (int j = g_head[v]; j >= 0; j = g_next[j]) {
        int ev = (j < EE) ? j : j - EE;
        if (ev < e && ev > best) best = ev;
    }
    if (t < EE) g_prev_s[e] = best;
    else        g_prev_d[e] = best;
}

// ---- persistent: dataflow singles with f32x2 math (R6 semantics, 32 warps/SM) ----
__global__ void __launch_bounds__(NTHR, 1) k_persist(
    const float* __restrict__ x, const int* __restrict__ ei, const float* __restrict__ eattr,
    const float* __restrict__ etime, const float* __restrict__ tw, const float* __restrict__ tb,
    const float* __restrict__ Wmsg, const float* __restrict__ bmsg,
    const float* __restrict__ Wih, const float* __restrict__ Whh,
    const float* __restrict__ blstm, float* __restrict__ out) {
    extern __shared__ float sm[];
    const int tid = threadIdx.x;
    const int lane = tid & 31;
    const int wid = tid >> 5;

    // stage weights (W_msg transposed, padded stride)
    for (int i = tid; i < 192 * 64; i += NTHR) {
        int k = i >> 6, j = i & 63;
        sm[OFF_WMT + j * WMT_STRIDE + k] = Wmsg[i];
    }
    {
        float4* d1 = (float4*)(sm + OFF_WIH);
        float4* d2 = (float4*)(sm + OFF_WHH);
        const float4* s1 = (const float4*)Wih;
        const float4* s2 = (const float4*)Whh;
        for (int i = tid; i < 4096; i += NTHR) { d1[i] = s1[i]; d2[i] = s2[i]; }
    }
    for (int i = tid; i < 64; i += NTHR) sm[OFF_BM + i] = bmsg[i];
    for (int i = tid; i < 256; i += NTHR) sm[OFF_BL + i] = blstm[i];
    if (tid < 32) { sm[OFF_TW + tid] = tw[tid]; sm[OFF_TB + tid] = tb[tid]; }
    __syncthreads();

    const int gw = blockIdx.x * NWARP + wid;
    float* sF = sm + OFF_FEAT + wid * 192;
    float* sMw = sm + OFF_M + wid * 128;
    volatile int* vdone = (volatile int*)g_done;

    for (int e = gw; e < EE; e += TOTWARP) {
        int s = ei[e], d = ei[EE + e];
        int ps = g_prev_s[e], pd = g_prev_d[e];
        if (lane == 0) {
            int spins = 0;
            while ((ps >= 0 && vdone[ps] == 0) || (pd >= 0 && vdone[pd] == 0)) {
                __nanosleep(40);
                if (++spins > 20000000) break;  // fail visibly, never hang
            }
        }
        __syncwarp();
        __threadfence();  // acquire: order after flags; drop stale L1 h/c lines

        // ---- stage features: [0:64)=hs [64:128)=hd [128:160)=ea [160:192)=te ----
        {
            float t = etime[e];
            sF[lane]       = g_h[(size_t)s * HH + lane];
            sF[32 + lane]  = g_h[(size_t)s * HH + 32 + lane];
            sF[64 + lane]  = g_h[(size_t)d * HH + lane];
            sF[96 + lane]  = g_h[(size_t)d * HH + 32 + lane];
            sF[128 + lane] = eattr[(size_t)e * EAA + lane];
            sF[160 + lane] = cosf(fmaf(t, sm[OFF_TW + lane], sm[OFF_TB + lane]));
        }
        __syncwarp();

        // ---- message GEMV via f32x2: acc pairs over adjacent k ----
        {
            const ulonglong2* w0p = (const ulonglong2*)(sm + OFF_WMT + lane * WMT_STRIDE);
            const ulonglong2* w1p = (const ulonglong2*)(sm + OFF_WMT + (lane + 32) * WMT_STRIDE);
            const ulonglong2* fv = (const ulonglong2*)sF;
            u64 a00 = pack2(sm[OFF_BM + lane], 0.0f);
            u64 a01 = pack2(sm[OFF_BM + 32 + lane], 0.0f);
            u64 a10 = a00, a11 = a01;
#pragma unroll
            for (int q = 0; q < 16; q++) {  // k[0,64): row0 -> hd, row1 -> hs
                ulonglong2 w0 = w0p[q], w1 = w1p[q];
                ulonglong2 f0 = fv[16 + q], f1 = fv[q];
                a00 = fma2(f0.x, w0.x, a00); a00 = fma2(f0.y, w0.y, a00);
                a01 = fma2(f0.x, w1.x, a01); a01 = fma2(f0.y, w1.y, a01);
                a10 = fma2(f1.x, w0.x, a10); a10 = fma2(f1.y, w0.y, a10);
                a11 = fma2(f1.x, w1.x, a11); a11 = fma2(f1.y, w1.y, a11);
            }
#pragma unroll
            for (int q = 16; q < 32; q++) {  // k[64,128): row0 -> hs, row1 -> hd
                ulonglong2 w0 = w0p[q], w1 = w1p[q];
                ulonglong2 f0 = fv[q - 16], f1 = fv[q];
                a00 = fma2(f0.x, w0.x, a00); a00 = fma2(f0.y, w0.y, a00);
                a01 = fma2(f0.x, w1.x, a01); a01 = fma2(f0.y, w1.y, a01);
                a10 = fma2(f1.x, w0.x, a10); a10 = fma2(f1.y, w0.y, a10);
                a11 = fma2(f1.x, w1.x, a11); a11 = fma2(f1.y, w1.y, a11);
            }
#pragma unroll
            for (int q = 32; q < 48; q++) {  // k[128,192): shared ea/te
                ulonglong2 w0 = w0p[q], w1 = w1p[q];
                ulonglong2 f = fv[q];
                a00 = fma2(f.x, w0.x, a00); a00 = fma2(f.y, w0.y, a00);
                a01 = fma2(f.x, w1.x, a01); a01 = fma2(f.y, w1.y, a01);
                a10 = fma2(f.x, w0.x, a10); a10 = fma2(f.y, w0.y, a10);
                a11 = fma2(f.x, w1.x, a11); a11 = fma2(f.y, w1.y, a11);
            }
            float2 p0 = unpack2(a00), p1 = unpack2(a01), p2 = unpack2(a10), p3 = unpack2(a11);
            sMw[lane]      = fmaxf(p0.x + p0.y, 0.0f);
            sMw[32 + lane] = fmaxf(p1.x + p1.y, 0.0f);
            sMw[64 + lane] = fmaxf(p2.x + p2.y, 0.0f);
            sMw[96 + lane] = fmaxf(p3.x + p3.y, 0.0f);
        }
        __syncwarp();

        // ---- LSTM gates via f32x2: acc pairs over adjacent output cols ----
        // sMw layout: [0:64) = row0 message, [64:128) = row1 message
        float acc0[8], acc1[8];
        {
            const ulonglong2* wih2 = (const ulonglong2*)(sm + OFF_WIH);
            const ulonglong2* whh2 = (const ulonglong2*)(sm + OFF_WHH);
            ulonglong2 bl_lo = *(const ulonglong2*)(sm + OFF_BL + 4 * lane);
            ulonglong2 bl_hi = *(const ulonglong2*)(sm + OFF_BL + 128 + 4 * lane);
            u64 A[4] = {bl_lo.x, bl_lo.y, bl_hi.x, bl_hi.y};
            u64 B[4] = {bl_lo.x, bl_lo.y, bl_hi.x, bl_hi.y};
#pragma unroll 4
            for (int k = 0; k < 64; k++) {
                float m0 = sMw[k], m1 = sMw[64 + k];
                float h0 = sF[k], h1 = sF[64 + k];
                u64 m0p = pack2(m0, m0), m1p = pack2(m1, m1);
                u64 h0p = pack2(h0, h0), h1p = pack2(h1, h1);
                ulonglong2 wa = wih2[(k << 6) + lane], wb = wih2[(k << 6) + 32 + lane];
                ulonglong2 ua = whh2[(k << 6) + lane], ub = whh2[(k << 6) + 32 + lane];
                A[0] = fma2(m0p, wa.x, A[0]); A[1] = fma2(m0p, wa.y, A[1]);
                A[2] = fma2(m0p, wb.x, A[2]); A[3] = fma2(m0p, wb.y, A[3]);
                A[0] = fma2(h0p, ua.x, A[0]); A[1] = fma2(h0p, ua.y, A[1]);
                A[2] = fma2(h0p, ub.x, A[2]); A[3] = fma2(h0p, ub.y, A[3]);
                B[0] = fma2(m1p, wa.x, B[0]); B[1] = fma2(m1p, wa.y, B[1]);
                B[2] = fma2(m1p, wb.x, B[2]); B[3] = fma2(m1p, wb.y, B[3]);
                B[0] = fma2(h1p, ua.x, B[0]); B[1] = fma2(h1p, ua.y, B[1]);
                B[2] = fma2(h1p, ub.x, B[2]); B[3] = fma2(h1p, ub.y, B[3]);
            }
#pragma unroll
            for (int j = 0; j < 4; j++) {
                float2 pa = unpack2(A[j]), pb = unpack2(B[j]);
                acc0[2 * j] = pa.x; acc0[2 * j + 1] = pa.y;
                acc1[2 * j] = pb.x; acc1[2 * j + 1] = pb.y;
            }
        }

        // ---- epilogue: lanes 0..15 = i|g, lanes 16..31 = f|o ----
        {
            float f0g[4], o0g[4], f1g[4], o1g[4];
#pragma unroll
            for (int c2 = 0; c2 < 4; c2++) {
                f0g[c2] = __shfl_down_sync(0xffffffffu, acc0[c2], 16);
                o0g[c2] = __shfl_down_sync(0xffffffffu, acc0[4 + c2], 16);
                f1g[c2] = __shfl_down_sync(0xffffffffu, acc1[c2], 16);
                o1g[c2] = __shfl_down_sync(0xffffffffu, acc1[4 + c2], 16);
            }
            if (lane < 16) {
                float4 c0 = *(const float4*)(g_c + (size_t)s * HH + 4 * lane);
                float4 c1 = *(const float4*)(g_c + (size_t)d * HH + 4 * lane);
                float c0a[4] = {c0.x, c0.y, c0.z, c0.w};
                float c1a[4] = {c1.x, c1.y, c1.z, c1.w};
                float cn0[4], hn0[4], cn1[4], hn1[4];
#pragma unroll
                for (int c2 = 0; c2 < 4; c2++) {
                    cn0[c2] = sigf(f0g[c2]) * c0a[c2] + sigf(acc0[c2]) * tanhf_(acc0[4 + c2]);
                    hn0[c2] = sigf(o0g[c2]) * tanhf_(cn0[c2]);
                    cn1[c2] = sigf(f1g[c2]) * c1a[c2] + sigf(acc1[c2]) * tanhf_(acc1[4 + c2]);
                    hn1[c2] = sigf(o1g[c2]) * tanhf_(cn1[c2]);
                }
                if (s != d) {  // src==dst: dst (row 1) update wins, matching scatter
                    *(float4*)(g_h + (size_t)s * HH + 4 * lane) = make_float4(hn0[0], hn0[1], hn0[2], hn0[3]);
                    *(float4*)(g_c + (size_t)s * HH + 4 * lane) = make_float4(cn0[0], cn0[1], cn0[2], cn0[3]);
                }
                *(float4*)(g_h + (size_t)d * HH + 4 * lane) = make_float4(hn1[0], hn1[1], hn1[2], hn1[3]);
                *(float4*)(g_c + (size_t)d * HH + 4 * lane) = make_float4(cn1[0], cn1[1], cn1[2], cn1[3]);
                __threadfence();  // each writer publishes its own stores
            }
        }
        __syncwarp();
        if (lane == 0) vdone[e] = 1;
        __syncwarp();
    }

    grid_bar();  // classifier needs FINAL h

    // ---- classifier: logits[e] = [h[dst] || x[dst]] @ Wc + bc ----
    for (int i = tid; i < 192 * AA; i += NTHR) sm[OFF_WMT + i] = g_Wc[i];
    for (int i = tid; i < AA; i += NTHR) sm[OFF_WMT + 9600 + i] = g_bc[i];
    __syncthreads();
    const float* sWc = sm + OFF_WMT;
    const float* sBc = sm + OFF_WMT + 9600;

    for (int e = gw; e < EE; e += TOTWARP) {
        int d = ei[EE + e];
        __syncwarp();
        sF[lane]      = g_h[(size_t)d * HH + lane];
        sF[32 + lane] = g_h[(size_t)d * HH + 32 + lane];
        {
            const float4* xv = (const float4*)(x + (size_t)d * DF);
            ((float4*)(sF + 64))[lane] = xv[lane];
        }
        __syncwarp();
        float r0 = sBc[lane];
        float r1 = (lane < AA - 32) ? sBc[32 + lane] : 0.0f;
        const float4* fvc = (const float4*)sF;
#pragma unroll 4
        for (int q = 0; q < 48; ++q) {
            float4 f = fvc[q];
            int kb = 4 * q;
            r0 = fmaf(f.x, sWc[(kb + 0) * AA + lane], r0);
            r0 = fmaf(f.y, sWc[(kb + 1) * AA + lane], r0);
            r0 = fmaf(f.z, sWc[(kb + 2) * AA + lane], r0);
            r0 = fmaf(f.w, sWc[(kb + 3) * AA + lane], r0);
            r1 = fmaf(f.x, sWc[(kb + 0) * AA + 32 + lane], r1);
            r1 = fmaf(f.y, sWc[(kb + 1) * AA + 32 + lane], r1);
            r1 = fmaf(f.z, sWc[(kb + 2) * AA + 32 + lane], r1);
            r1 = fmaf(f.w, sWc[(kb + 3) * AA + 32 + lane], r1);
        }
        float* op = out + (size_t)e * AA;
        op[lane] = r0;
        if (lane < AA - 32) op[32 + lane] = r1;
    }
}

extern "C" void kernel_launch(void* const* d_in, const int* in_sizes, int n_in,
                              void* d_out, int out_size) {
    const float* x     = (const float*)d_in[0];
    const int*   ei    = (const int*)d_in[1];
    const float* eattr = (const float*)d_in[2];
    const float* etime = (const float*)d_in[3];
    const float* tw    = (const float*)d_in[4];
    const float* tb    = (const float*)d_in[5];
    const float* Wmsg  = (const float*)d_in[6];
    const float* bmsg  = (const float*)d_in[7];
    const float* Wih   = (const float*)d_in[8];
    const float* Whh   = (const float*)d_in[9];
    const float* blstm = (const float*)d_in[10];
    const float* Wemb  = (const float*)d_in[11];
    const float* bemb  = (const float*)d_in[12];
    const float* Wcls  = (const float*)d_in[13];
    const float* bcls  = (const float*)d_in[14];
    float* out = (float*)d_out;

    cudaFuncSetAttribute(k_persist, cudaFuncAttributeMaxDynamicSharedMemorySize, SMEM_BYTES);

    k_init<<<128, 512>>>(ei, Wemb, bemb, Wcls, bcls);
    k_chain<<<32, 512>>>(ei);
    k_prevk<<<32, 512>>>(ei);
    k_persist<<<NBLK, NTHR, SMEM_BYTES>>>(x, ei, eattr, etime, tw, tb, Wmsg, bmsg, Wih, Whh,
                                          blstm, out);
}